// round 8
// baseline (speedup 1.0000x reference)
#include <cuda_runtime.h>
#include <cstdint>

#define NN    10000
#define EE    160000
#define INDIM 1000
#define HID   256
#define OUTD  2

// ---------------- scratch (static __device__, no runtime alloc) ----------------
__device__ float g_xw1[NN * HID];   // features @ W1
__device__ float g_hw2[NN * OUTD];  // relu(gcn1) @ W2
__device__ float g_dinv[NN];
__device__ float g_sq[NN];
__device__ int   g_deg[NN];
__device__ int   g_cur[NN];
__device__ int   g_off[NN + 1];
__device__ int   g_srcv[EE];

// ================= helpers =================
__device__ __forceinline__ uint32_t smem_u32(const void* p) {
    uint32_t a;
    asm("{ .reg .u64 t; cvta.to.shared.u64 t, %1; cvt.u32.u64 %0, t; }"
        : "=r"(a) : "l"(p));
    return a;
}

__device__ __forceinline__ void cp16(uint32_t dst, const void* src, int sz) {
    asm volatile("cp.async.cg.shared.global [%0], [%1], 16, %2;"
                 :: "r"(dst), "l"(src), "r"(sz) : "memory");
}

__device__ __forceinline__ uint32_t tf32r(float x) {
    uint32_t u;
    asm("cvt.rna.tf32.f32 %0, %1;" : "=r"(u) : "f"(x));
    return u;
}

__device__ __forceinline__ void mma_tf32(float* d, const uint32_t* a, const uint32_t* b) {
    asm volatile(
        "mma.sync.aligned.m16n8k8.row.col.f32.tf32.tf32.f32 "
        "{%0,%1,%2,%3}, {%4,%5,%6,%7}, {%8,%9}, {%0,%1,%2,%3};"
        : "+f"(d[0]), "+f"(d[1]), "+f"(d[2]), "+f"(d[3])
        : "r"(a[0]), "r"(a[1]), "r"(a[2]), "r"(a[3]), "r"(b[0]), "r"(b[1]));
}

// ---------------- CSR build ----------------
__global__ void k_zero_deg() {
    int i = blockIdx.x * blockDim.x + threadIdx.x;
    if (i < NN) g_deg[i] = 0;
}

__global__ void k_count(const int* __restrict__ ei) {
    int i = blockIdx.x * blockDim.x + threadIdx.x;
    if (i < EE / 4) {
        int4 d = ((const int4*)(ei + EE))[i];
        atomicAdd(&g_deg[d.x], 1);
        atomicAdd(&g_deg[d.y], 1);
        atomicAdd(&g_deg[d.z], 1);
        atomicAdd(&g_deg[d.w], 1);
    }
}

__global__ void k_scan() {
    __shared__ int part[256];
    __shared__ int excl[257];
    int t = threadIdx.x;
    const int CH = (NN + 255) / 256;
    int base = t * CH;
    int s = 0;
    for (int i = 0; i < CH; i++) {
        int idx = base + i;
        if (idx < NN) s += g_deg[idx];
    }
    part[t] = s;
    __syncthreads();
    if (t == 0) {
        int run = 0;
        for (int i = 0; i < 256; i++) { excl[i] = run; run += part[i]; }
        excl[256] = run;
    }
    __syncthreads();
    int off = excl[t];
    for (int i = 0; i < CH; i++) {
        int idx = base + i;
        if (idx < NN) {
            g_off[idx] = off;
            g_cur[idx] = off;
            int d = g_deg[idx];
            off += d;
            g_dinv[idx] = rsqrtf((float)(d + 1));
        }
    }
    if (t == 255) g_off[NN] = excl[256];
}

__global__ void k_scatter(const int* __restrict__ ei) {
    int i = blockIdx.x * blockDim.x + threadIdx.x;
    if (i < EE / 4) {
        int4 sv = ((const int4*)ei)[i];
        int4 dv = ((const int4*)(ei + EE))[i];
        g_srcv[atomicAdd(&g_cur[dv.x], 1)] = sv.x;
        g_srcv[atomicAdd(&g_cur[dv.y], 1)] = sv.y;
        g_srcv[atomicAdd(&g_cur[dv.z], 1)] = sv.z;
        g_srcv[atomicAdd(&g_cur[dv.w], 1)] = sv.w;
    }
}

// ---------------- GEMM1 via mma.sync tf32: features[10000,1000] @ W1[1000,256] ----------------
// CTA tile M=128, N=128, K=16/stage; 3-stage cp.async; 256 thr, warps 4M x 2N (warp tile 32x64).
#define A_STRIDE 20
#define B_STRIDE 136
#define A_FLOATS (128 * A_STRIDE)                 // 2560
#define STAGE_F  (A_FLOATS + 16 * B_STRIDE)       // 4736 floats = 18944 B
#define GEMM_SMEM (3 * STAGE_F * 4)               // 56832 B
#define NCH      63

__device__ __forceinline__ void g1_load(float* smbase, int c, int ctaRow0, int n0,
                                        const float* __restrict__ A,
                                        const float* __restrict__ B) {
    if (c < NCH) {
        int k0 = c * 16;
        float* As = smbase + (c % 3) * STAGE_F;
        float* Bs = As + A_FLOATS;
        int tid = threadIdx.x;
        // A: 128 rows x 4 chunks of 16B = 512 cp16 -> 2/thread
#pragma unroll
        for (int j = 0; j < 2; j++) {
            int idx = tid + j * 256;
            int row = idx >> 2, seg = idx & 3;
            int kf = k0 + seg * 4;
            int gr = ctaRow0 + row;
            bool v = (kf + 4 <= INDIM) && (gr < NN);
            uint32_t dst = smem_u32(As + row * A_STRIDE) + seg * 16;
            cp16(dst, A + (v ? (size_t)gr * INDIM + kf : 0), v ? 16 : 0);
        }
        // B: 16 rows x 32 chunks of 16B = 512 cp16 -> 2/thread
#pragma unroll
        for (int j = 0; j < 2; j++) {
            int idx = tid + j * 256;
            int row = idx >> 5, seg = idx & 31;
            bool v = (k0 + row) < INDIM;
            uint32_t dst = smem_u32(Bs + row * B_STRIDE) + seg * 16;
            cp16(dst, B + (v ? (size_t)(k0 + row) * HID + n0 + seg * 4 : 0), v ? 16 : 0);
        }
    }
    asm volatile("cp.async.commit_group;" ::: "memory");
}

__global__ __launch_bounds__(256) void k_gemm_mma(const float* __restrict__ A,
                                                  const float* __restrict__ B) {
    extern __shared__ __align__(16) float sm[];
    int tid = threadIdx.x;
    int warp = tid >> 5, lane = tid & 31;
    int g = lane >> 2, tig = lane & 3;
    int wm = (warp >> 1) * 32;       // 0,32,64,96
    int wn = (warp & 1) * 64;        // 0,64
    int ctaRow0 = blockIdx.y * 128;
    int n0 = blockIdx.x * 128;

    float d[2][8][4];
#pragma unroll
    for (int mt = 0; mt < 2; mt++)
#pragma unroll
        for (int nt = 0; nt < 8; nt++)
#pragma unroll
            for (int r = 0; r < 4; r++) d[mt][nt][r] = 0.0f;

    g1_load(sm, 0, ctaRow0, n0, A, B);
    g1_load(sm, 1, ctaRow0, n0, A, B);

    for (int c = 0; c < NCH; c++) {
        asm volatile("cp.async.wait_group 1;" ::: "memory");
        __syncthreads();
        g1_load(sm, c + 2, ctaRow0, n0, A, B);

        const float* As = sm + (c % 3) * STAGE_F;
        const float* Bs = As + A_FLOATS;
#pragma unroll
        for (int ks = 0; ks < 2; ks++) {
            int kb = ks * 8;
            uint32_t af[2][4], bf[8][2];
#pragma unroll
            for (int mt = 0; mt < 2; mt++) {
                int m = wm + mt * 16 + g;
                af[mt][0] = tf32r(As[m * A_STRIDE + kb + tig]);
                af[mt][1] = tf32r(As[(m + 8) * A_STRIDE + kb + tig]);
                af[mt][2] = tf32r(As[m * A_STRIDE + kb + tig + 4]);
                af[mt][3] = tf32r(As[(m + 8) * A_STRIDE + kb + tig + 4]);
            }
#pragma unroll
            for (int nt = 0; nt < 8; nt++) {
                int n = wn + nt * 8 + g;
                bf[nt][0] = tf32r(Bs[(kb + tig) * B_STRIDE + n]);
                bf[nt][1] = tf32r(Bs[(kb + tig + 4) * B_STRIDE + n]);
            }
#pragma unroll
            for (int mt = 0; mt < 2; mt++)
#pragma unroll
                for (int nt = 0; nt < 8; nt++)
                    mma_tf32(d[mt][nt], af[mt], bf[nt]);
        }
        __syncthreads();
    }

#pragma unroll
    for (int mt = 0; mt < 2; mt++) {
        int row0 = ctaRow0 + wm + mt * 16 + g;
#pragma unroll
        for (int nt = 0; nt < 8; nt++) {
            int col = n0 + wn + nt * 8 + 2 * tig;
            if (row0 < NN)
                *(float2*)&g_xw1[(size_t)row0 * HID + col] =
                    make_float2(d[mt][nt][0], d[mt][nt][1]);
            if (row0 + 8 < NN)
                *(float2*)&g_xw1[(size_t)(row0 + 8) * HID + col] =
                    make_float2(d[mt][nt][2], d[mt][nt][3]);
        }
    }
}

// ---------------- fused agg1 + bias + relu + W2 projection -> g_hw2 ----------------
__global__ void k_agg1(const float* __restrict__ b1, const float* __restrict__ W2) {
    int w = (blockIdx.x * blockDim.x + threadIdx.x) >> 5;
    int lane = threadIdx.x & 31;
    if (w >= NN) return;
    float di = g_dinv[w];
    float acc[8];
    const float* xi = g_xw1 + (size_t)w * HID;
#pragma unroll
    for (int u = 0; u < 8; u++) acc[u] = di * xi[u * 32 + lane];
    int p0 = g_off[w], p1 = g_off[w + 1];
    for (int p = p0; p < p1; p++) {
        int s = g_srcv[p];
        float ds = g_dinv[s];
        const float* xs = g_xw1 + (size_t)s * HID;
#pragma unroll
        for (int u = 0; u < 8; u++) acc[u] = fmaf(ds, xs[u * 32 + lane], acc[u]);
    }
    float a0 = 0.f, a1 = 0.f;
#pragma unroll
    for (int u = 0; u < 8; u++) {
        int f = u * 32 + lane;
        float h = fmaxf(fmaf(di, acc[u], b1[f]), 0.0f);
        a0 = fmaf(h, W2[f * 2 + 0], a0);
        a1 = fmaf(h, W2[f * 2 + 1], a1);
    }
#pragma unroll
    for (int o = 16; o > 0; o >>= 1) {
        a0 += __shfl_down_sync(0xffffffffu, a0, o);
        a1 += __shfl_down_sync(0xffffffffu, a1, o);
    }
    if (lane == 0) {
        g_hw2[w * 2 + 0] = a0;
        g_hw2[w * 2 + 1] = a1;
    }
}

// ---------------- agg2 + bias -> emb (d_out) and sq ----------------
__global__ void k_agg2(const float* __restrict__ b2, float* __restrict__ emb) {
    int i = blockIdx.x * blockDim.x + threadIdx.x;
    if (i >= NN) return;
    float di = g_dinv[i];
    float a0 = di * g_hw2[i * 2 + 0];
    float a1 = di * g_hw2[i * 2 + 1];
    int p0 = g_off[i], p1 = g_off[i + 1];
    for (int p = p0; p < p1; p++) {
        int s = g_srcv[p];
        float ds = g_dinv[s];
        a0 = fmaf(ds, g_hw2[s * 2 + 0], a0);
        a1 = fmaf(ds, g_hw2[s * 2 + 1], a1);
    }
    float e0 = fmaf(di, a0, b2[0]);
    float e1 = fmaf(di, a1, b2[1]);
    emb[i * 2 + 0] = e0;
    emb[i * 2 + 1] = e1;
    g_sq[i] = e0 * e0 + e1 * e1;
}

// ---------------- q matrix: q = 1/(1 + 0.5*dist), streaming float4 stores ----------------
#define TJ 1024
#define TI 16

__device__ __forceinline__ float qval(float d2) {
    float d2c = fmaxf(d2, 1e-30f);
    float dist = d2c * rsqrtf(d2c);
    return __fdividef(1.0f, fmaf(0.5f, dist, 1.0f));
}

__global__ __launch_bounds__(256) void k_q(const float* __restrict__ emb,
                                           float* __restrict__ q) {
    __shared__ float sx[TJ], sy[TJ], ss[TJ];
    int j0 = blockIdx.x * TJ;
    int i0 = blockIdx.y * TI;
    int t = threadIdx.x;
#pragma unroll
    for (int v = 0; v < 4; v++) {
        int jl = t + v * 256;
        int jj = j0 + jl;
        if (jj < NN) {
            sx[jl] = emb[jj * 2 + 0];
            sy[jl] = emb[jj * 2 + 1];
            ss[jl] = g_sq[jj];
        }
    }
    __syncthreads();
    int jl = t * 4;
    int j = j0 + jl;
    if (j >= NN) return;
    float x0 = sx[jl], x1 = sx[jl + 1], x2 = sx[jl + 2], x3 = sx[jl + 3];
    float y0 = sy[jl], y1 = sy[jl + 1], y2 = sy[jl + 2], y3 = sy[jl + 3];
    float s0 = ss[jl], s1 = ss[jl + 1], s2 = ss[jl + 2], s3 = ss[jl + 3];
#pragma unroll
    for (int r = 0; r < TI; r++) {
        int i = i0 + r;
        float ex = emb[i * 2 + 0];
        float ey = emb[i * 2 + 1];
        float si = g_sq[i];
        float4 o;
        o.x = qval(si + s0 - 2.0f * fmaf(ex, x0, ey * y0));
        o.y = qval(si + s1 - 2.0f * fmaf(ex, x1, ey * y1));
        o.z = qval(si + s2 - 2.0f * fmaf(ex, x2, ey * y2));
        o.w = qval(si + s3 - 2.0f * fmaf(ex, x3, ey * y3));
        __stcs((float4*)(q + (size_t)i * NN + j), o);
    }
}

// ---------------- launch ----------------
extern "C" void kernel_launch(void* const* d_in, const int* in_sizes, int n_in,
                              void* d_out, int out_size) {
    const float* features = (const float*)d_in[0];
    const int*   ei       = (const int*)d_in[1];
    const float* W1       = (const float*)d_in[2];
    const float* b1       = (const float*)d_in[3];
    const float* W2       = (const float*)d_in[4];
    const float* b2       = (const float*)d_in[5];
    float* out = (float*)d_out;
    float* emb = out;                 // [NN, 2]
    float* q   = out + NN * OUTD;     // [NN, NN]

    cudaFuncSetAttribute(k_gemm_mma, cudaFuncAttributeMaxDynamicSharedMemorySize, GEMM_SMEM);

    k_zero_deg<<<(NN + 255) / 256, 256>>>();                 // 0
    k_count<<<(EE / 4 + 255) / 256, 256>>>(ei);              // 1
    k_scan<<<1, 256>>>();                                    // 2

    dim3 gg(HID / 128, (NN + 127) / 128);  // (2, 79)
    k_gemm_mma<<<gg, 256, GEMM_SMEM>>>(features, W1);        // 3 (profiled slot)

    k_scatter<<<(EE / 4 + 255) / 256, 256>>>(ei);            // 4
    k_agg1<<<(NN * 32 + 255) / 256, 256>>>(b1, W2);          // 5
    k_agg2<<<(NN + 255) / 256, 256>>>(b2, emb);              // 6

    dim3 gq((NN + TJ - 1) / TJ, NN / TI);
    k_q<<<gq, 256>>>(emb, q);                                // 7
}

// round 9
// speedup vs baseline: 1.1052x; 1.1052x over previous
#include <cuda_runtime.h>
#include <cstdint>

#define NN    10000
#define EE    160000
#define INDIM 1000
#define HID   256
#define OUTD  2

// ---------------- scratch (static __device__, no runtime alloc) ----------------
__device__ float g_xw1[NN * HID];    // features @ W1
__device__ float g_hw2[NN * OUTD];   // relu(gcn1) @ W2
__device__ float g_w1r[INDIM * HID]; // rna-tf32-rounded W1 (1MB, L2-resident)
__device__ float g_dinv[NN];
__device__ float g_sq[NN];
__device__ int   g_deg[NN];
__device__ int   g_cur[NN];
__device__ int   g_off[NN + 1];
__device__ int   g_srcv[EE];

// ================= helpers =================
__device__ __forceinline__ uint32_t smem_u32(const void* p) {
    uint32_t a;
    asm("{ .reg .u64 t; cvta.to.shared.u64 t, %1; cvt.u32.u64 %0, t; }"
        : "=r"(a) : "l"(p));
    return a;
}

__device__ __forceinline__ void cp16(uint32_t dst, const void* src, int sz) {
    asm volatile("cp.async.cg.shared.global [%0], [%1], 16, %2;"
                 :: "r"(dst), "l"(src), "r"(sz) : "memory");
}

__device__ __forceinline__ uint32_t tf32r(float x) {
    uint32_t u;
    asm("cvt.rna.tf32.f32 %0, %1;" : "=r"(u) : "f"(x));
    return u;
}

__device__ __forceinline__ void mma_tf32(float* d, const uint32_t* a, const uint32_t* b) {
    asm volatile(
        "mma.sync.aligned.m16n8k8.row.col.f32.tf32.tf32.f32 "
        "{%0,%1,%2,%3}, {%4,%5,%6,%7}, {%8,%9}, {%0,%1,%2,%3};"
        : "+f"(d[0]), "+f"(d[1]), "+f"(d[2]), "+f"(d[3])
        : "r"(a[0]), "r"(a[1]), "r"(a[2]), "r"(a[3]), "r"(b[0]), "r"(b[1]));
}

// ---------------- W1 pre-round (fp32 -> nearest tf32) ----------------
__global__ void k_roundW(const float* __restrict__ W1) {
    int i = blockIdx.x * blockDim.x + threadIdx.x;
    if (i < INDIM * HID / 4) {
        float4 v = ((const float4*)W1)[i];
        v.x = __uint_as_float(tf32r(v.x));
        v.y = __uint_as_float(tf32r(v.y));
        v.z = __uint_as_float(tf32r(v.z));
        v.w = __uint_as_float(tf32r(v.w));
        ((float4*)g_w1r)[i] = v;
    }
}

// ---------------- CSR build ----------------
__global__ void k_zero_deg() {
    int i = blockIdx.x * blockDim.x + threadIdx.x;
    if (i < NN) g_deg[i] = 0;
}

__global__ void k_count(const int* __restrict__ ei) {
    int i = blockIdx.x * blockDim.x + threadIdx.x;
    if (i < EE / 4) {
        int4 d = ((const int4*)(ei + EE))[i];
        atomicAdd(&g_deg[d.x], 1);
        atomicAdd(&g_deg[d.y], 1);
        atomicAdd(&g_deg[d.z], 1);
        atomicAdd(&g_deg[d.w], 1);
    }
}

__global__ void k_scan() {
    __shared__ int part[256];
    __shared__ int excl[257];
    int t = threadIdx.x;
    const int CH = (NN + 255) / 256;
    int base = t * CH;
    int s = 0;
    for (int i = 0; i < CH; i++) {
        int idx = base + i;
        if (idx < NN) s += g_deg[idx];
    }
    part[t] = s;
    __syncthreads();
    if (t == 0) {
        int run = 0;
        for (int i = 0; i < 256; i++) { excl[i] = run; run += part[i]; }
        excl[256] = run;
    }
    __syncthreads();
    int off = excl[t];
    for (int i = 0; i < CH; i++) {
        int idx = base + i;
        if (idx < NN) {
            g_off[idx] = off;
            g_cur[idx] = off;
            int d = g_deg[idx];
            off += d;
            g_dinv[idx] = rsqrtf((float)(d + 1));
        }
    }
    if (t == 255) g_off[NN] = excl[256];
}

__global__ void k_scatter(const int* __restrict__ ei) {
    int i = blockIdx.x * blockDim.x + threadIdx.x;
    if (i < EE / 4) {
        int4 sv = ((const int4*)ei)[i];
        int4 dv = ((const int4*)(ei + EE))[i];
        g_srcv[atomicAdd(&g_cur[dv.x], 1)] = sv.x;
        g_srcv[atomicAdd(&g_cur[dv.y], 1)] = sv.y;
        g_srcv[atomicAdd(&g_cur[dv.z], 1)] = sv.z;
        g_srcv[atomicAdd(&g_cur[dv.w], 1)] = sv.w;
    }
}

// ---------------- GEMM1 via mma.sync tf32: features[10000,1000] @ W1r[1000,256] ----------------
// CTA tile M=64, N=128, K=16/stage; 3-stage cp.async; 256 thr, warps 2M x 4N (warp 32x32).
#define A_STRIDE 20
#define B_STRIDE 136
#define A_FLOATS (64 * A_STRIDE)              // 1280
#define STAGE_F  (A_FLOATS + 16 * B_STRIDE)   // 3456 floats = 13824 B
#define NCH      63

__device__ __forceinline__ void g1_load(float* smbase, int c, int ctaRow0, int n0,
                                        const float* __restrict__ A) {
    if (c < NCH) {
        int k0 = c * 16;
        float* As = smbase + (c % 3) * STAGE_F;
        float* Bs = As + A_FLOATS;
        int tid = threadIdx.x;
        // A: 64 rows x 4 chunks of 16B -> 256 cp16 (1/thread)
        {
            int row = tid >> 2, seg = tid & 3;
            int kf = k0 + seg * 4;
            int gr = ctaRow0 + row;
            bool v = (kf + 4 <= INDIM) && (gr < NN);
            uint32_t dst = smem_u32(As + row * A_STRIDE) + seg * 16;
            cp16(dst, A + (v ? (size_t)gr * INDIM + kf : 0), v ? 16 : 0);
        }
        // B: 16 rows x 32 chunks of 16B -> 512 cp16 (2/thread)
#pragma unroll
        for (int j = 0; j < 2; j++) {
            int idx = tid + j * 256;
            int row = idx >> 5, seg = idx & 31;
            bool v = (k0 + row) < INDIM;
            uint32_t dst = smem_u32(Bs + row * B_STRIDE) + seg * 16;
            cp16(dst, g_w1r + (v ? (size_t)(k0 + row) * HID + n0 + seg * 4 : 0), v ? 16 : 0);
        }
    }
    asm volatile("cp.async.commit_group;" ::: "memory");
}

__global__ __launch_bounds__(256) void k_gemm_mma(const float* __restrict__ A) {
    __shared__ __align__(16) float sm[3 * STAGE_F];  // 41472 B
    int tid = threadIdx.x;
    int warp = tid >> 5, lane = tid & 31;
    int g = lane >> 2, tig = lane & 3;
    int wm = (warp >> 2) * 32;       // 0 or 32
    int wn = (warp & 3) * 32;        // 0..96
    int ctaRow0 = blockIdx.y * 64;
    int n0 = blockIdx.x * 128;

    float d[2][4][4];
#pragma unroll
    for (int mt = 0; mt < 2; mt++)
#pragma unroll
        for (int nt = 0; nt < 4; nt++)
#pragma unroll
            for (int r = 0; r < 4; r++) d[mt][nt][r] = 0.0f;

    g1_load(sm, 0, ctaRow0, n0, A);
    g1_load(sm, 1, ctaRow0, n0, A);

    for (int c = 0; c < NCH; c++) {
        asm volatile("cp.async.wait_group 1;" ::: "memory");
        __syncthreads();           // single barrier per chunk (see hazard analysis)
        g1_load(sm, c + 2, ctaRow0, n0, A);

        const float* As = sm + (c % 3) * STAGE_F;
        const float* Bs = As + A_FLOATS;
#pragma unroll
        for (int ks = 0; ks < 2; ks++) {
            int kb = ks * 8;
            uint32_t af[2][4], bf[4][2];
#pragma unroll
            for (int mt = 0; mt < 2; mt++) {
                int m = wm + mt * 16 + g;
                af[mt][0] = tf32r(As[m * A_STRIDE + kb + tig]);
                af[mt][1] = tf32r(As[(m + 8) * A_STRIDE + kb + tig]);
                af[mt][2] = tf32r(As[m * A_STRIDE + kb + tig + 4]);
                af[mt][3] = tf32r(As[(m + 8) * A_STRIDE + kb + tig + 4]);
            }
#pragma unroll
            for (int nt = 0; nt < 4; nt++) {
                int n = wn + nt * 8 + g;
                bf[nt][0] = __float_as_uint(Bs[(kb + tig) * B_STRIDE + n]);      // pre-rounded
                bf[nt][1] = __float_as_uint(Bs[(kb + tig + 4) * B_STRIDE + n]);
            }
#pragma unroll
            for (int mt = 0; mt < 2; mt++)
#pragma unroll
                for (int nt = 0; nt < 4; nt++)
                    mma_tf32(d[mt][nt], af[mt], bf[nt]);
        }
    }

#pragma unroll
    for (int mt = 0; mt < 2; mt++) {
        int row0 = ctaRow0 + wm + mt * 16 + g;
#pragma unroll
        for (int nt = 0; nt < 4; nt++) {
            int col = n0 + wn + nt * 8 + 2 * tig;
            if (row0 < NN)
                *(float2*)&g_xw1[(size_t)row0 * HID + col] =
                    make_float2(d[mt][nt][0], d[mt][nt][1]);
            if (row0 + 8 < NN)
                *(float2*)&g_xw1[(size_t)(row0 + 8) * HID + col] =
                    make_float2(d[mt][nt][2], d[mt][nt][3]);
        }
    }
}

// ---------------- fused agg1 + bias + relu + W2 projection -> g_hw2 ----------------
__global__ void k_agg1(const float* __restrict__ b1, const float* __restrict__ W2) {
    int w = (blockIdx.x * blockDim.x + threadIdx.x) >> 5;
    int lane = threadIdx.x & 31;
    if (w >= NN) return;
    float di = g_dinv[w];
    float acc[8];
    const float* xi = g_xw1 + (size_t)w * HID;
#pragma unroll
    for (int u = 0; u < 8; u++) acc[u] = di * xi[u * 32 + lane];
    int p0 = g_off[w], p1 = g_off[w + 1];
    for (int p = p0; p < p1; p++) {
        int s = g_srcv[p];
        float ds = g_dinv[s];
        const float* xs = g_xw1 + (size_t)s * HID;
#pragma unroll
        for (int u = 0; u < 8; u++) acc[u] = fmaf(ds, xs[u * 32 + lane], acc[u]);
    }
    float a0 = 0.f, a1 = 0.f;
#pragma unroll
    for (int u = 0; u < 8; u++) {
        int f = u * 32 + lane;
        float h = fmaxf(fmaf(di, acc[u], b1[f]), 0.0f);
        a0 = fmaf(h, W2[f * 2 + 0], a0);
        a1 = fmaf(h, W2[f * 2 + 1], a1);
    }
#pragma unroll
    for (int o = 16; o > 0; o >>= 1) {
        a0 += __shfl_down_sync(0xffffffffu, a0, o);
        a1 += __shfl_down_sync(0xffffffffu, a1, o);
    }
    if (lane == 0) {
        g_hw2[w * 2 + 0] = a0;
        g_hw2[w * 2 + 1] = a1;
    }
}

// ---------------- agg2 + bias -> emb (d_out) and sq ----------------
__global__ void k_agg2(const float* __restrict__ b2, float* __restrict__ emb) {
    int i = blockIdx.x * blockDim.x + threadIdx.x;
    if (i >= NN) return;
    float di = g_dinv[i];
    float a0 = di * g_hw2[i * 2 + 0];
    float a1 = di * g_hw2[i * 2 + 1];
    int p0 = g_off[i], p1 = g_off[i + 1];
    for (int p = p0; p < p1; p++) {
        int s = g_srcv[p];
        float ds = g_dinv[s];
        a0 = fmaf(ds, g_hw2[s * 2 + 0], a0);
        a1 = fmaf(ds, g_hw2[s * 2 + 1], a1);
    }
    float e0 = fmaf(di, a0, b2[0]);
    float e1 = fmaf(di, a1, b2[1]);
    emb[i * 2 + 0] = e0;
    emb[i * 2 + 1] = e1;
    g_sq[i] = e0 * e0 + e1 * e1;
}

// ---------------- q matrix: q = 1/(1 + 0.5*dist), streaming float4 stores ----------------
#define TJ 1024
#define TI 16

__device__ __forceinline__ float qval(float d2) {
    float d2c = fmaxf(d2, 1e-30f);
    float dist = d2c * rsqrtf(d2c);
    return __fdividef(1.0f, fmaf(0.5f, dist, 1.0f));
}

__global__ __launch_bounds__(256) void k_q(const float* __restrict__ emb,
                                           float* __restrict__ q) {
    __shared__ float sx[TJ], sy[TJ], ss[TJ];
    int j0 = blockIdx.x * TJ;
    int i0 = blockIdx.y * TI;
    int t = threadIdx.x;
#pragma unroll
    for (int v = 0; v < 4; v++) {
        int jl = t + v * 256;
        int jj = j0 + jl;
        if (jj < NN) {
            sx[jl] = emb[jj * 2 + 0];
            sy[jl] = emb[jj * 2 + 1];
            ss[jl] = g_sq[jj];
        }
    }
    __syncthreads();
    int jl = t * 4;
    int j = j0 + jl;
    if (j >= NN) return;
    float x0 = sx[jl], x1 = sx[jl + 1], x2 = sx[jl + 2], x3 = sx[jl + 3];
    float y0 = sy[jl], y1 = sy[jl + 1], y2 = sy[jl + 2], y3 = sy[jl + 3];
    float s0 = ss[jl], s1 = ss[jl + 1], s2 = ss[jl + 2], s3 = ss[jl + 3];
#pragma unroll
    for (int r = 0; r < TI; r++) {
        int i = i0 + r;
        float ex = emb[i * 2 + 0];
        float ey = emb[i * 2 + 1];
        float si = g_sq[i];
        float4 o;
        o.x = qval(si + s0 - 2.0f * fmaf(ex, x0, ey * y0));
        o.y = qval(si + s1 - 2.0f * fmaf(ex, x1, ey * y1));
        o.z = qval(si + s2 - 2.0f * fmaf(ex, x2, ey * y2));
        o.w = qval(si + s3 - 2.0f * fmaf(ex, x3, ey * y3));
        __stcs((float4*)(q + (size_t)i * NN + j), o);
    }
}

// ---------------- launch ----------------
extern "C" void kernel_launch(void* const* d_in, const int* in_sizes, int n_in,
                              void* d_out, int out_size) {
    const float* features = (const float*)d_in[0];
    const int*   ei       = (const int*)d_in[1];
    const float* W1       = (const float*)d_in[2];
    const float* b1       = (const float*)d_in[3];
    const float* W2       = (const float*)d_in[4];
    const float* b2       = (const float*)d_in[5];
    float* out = (float*)d_out;
    float* emb = out;                 // [NN, 2]
    float* q   = out + NN * OUTD;     // [NN, NN]

    k_roundW<<<(INDIM * HID / 4 + 255) / 256, 256>>>(W1);    // 0
    k_zero_deg<<<(NN + 255) / 256, 256>>>();                 // 1
    k_count<<<(EE / 4 + 255) / 256, 256>>>(ei);              // 2

    dim3 gg(HID / 128, (NN + 63) / 64);  // (1, 157) -> wait HID/128 = 2 -> (2,157) = 314 CTAs
    k_gemm_mma<<<gg, 256>>>(features);                       // 3 (profiled slot)

    k_scan<<<1, 256>>>();                                    // 4
    k_scatter<<<(EE / 4 + 255) / 256, 256>>>(ei);            // 5
    k_agg1<<<(NN * 32 + 255) / 256, 256>>>(b1, W2);          // 6
    k_agg2<<<(NN + 255) / 256, 256>>>(b2, emb);              // 7

    dim3 gq((NN + TJ - 1) / TJ, NN / TI);
    k_q<<<gq, 256>>>(emb, q);                                // 8
}

// round 10
// speedup vs baseline: 1.1190x; 1.0125x over previous
#include <cuda_runtime.h>
#include <cstdint>

#define NN    10000
#define EE    160000
#define INDIM 1000
#define HID   256
#define OUTD  2

// ---------------- scratch (static __device__, no runtime alloc) ----------------
__device__ float g_xw1[NN * HID];    // features @ W1
__device__ float g_hw2[NN * OUTD];   // relu(gcn1) @ W2
__device__ float g_w1r[INDIM * HID]; // rna-tf32-rounded W1 (1MB, L2-resident)
__device__ float g_dinv[NN];
__device__ float g_sq[NN];
__device__ int   g_deg[NN];
__device__ int   g_cur[NN];
__device__ int   g_off[NN + 1];
__device__ int   g_srcv[EE];

// ================= helpers =================
__device__ __forceinline__ uint32_t smem_u32(const void* p) {
    uint32_t a;
    asm("{ .reg .u64 t; cvta.to.shared.u64 t, %1; cvt.u32.u64 %0, t; }"
        : "=r"(a) : "l"(p));
    return a;
}

__device__ __forceinline__ void cp16(uint32_t dst, const void* src, int sz) {
    asm volatile("cp.async.cg.shared.global [%0], [%1], 16, %2;"
                 :: "r"(dst), "l"(src), "r"(sz) : "memory");
}

__device__ __forceinline__ uint32_t tf32r(float x) {
    uint32_t u;
    asm("cvt.rna.tf32.f32 %0, %1;" : "=r"(u) : "f"(x));
    return u;
}

__device__ __forceinline__ void mma_tf32(float* d, const uint32_t* a, const uint32_t* b) {
    asm volatile(
        "mma.sync.aligned.m16n8k8.row.col.f32.tf32.tf32.f32 "
        "{%0,%1,%2,%3}, {%4,%5,%6,%7}, {%8,%9}, {%0,%1,%2,%3};"
        : "+f"(d[0]), "+f"(d[1]), "+f"(d[2]), "+f"(d[3])
        : "r"(a[0]), "r"(a[1]), "r"(a[2]), "r"(a[3]), "r"(b[0]), "r"(b[1]));
}

// ---------------- W1 pre-round (fp32 -> nearest tf32) ----------------
__global__ void k_roundW(const float* __restrict__ W1) {
    int i = blockIdx.x * blockDim.x + threadIdx.x;
    if (i < INDIM * HID / 4) {
        float4 v = ((const float4*)W1)[i];
        v.x = __uint_as_float(tf32r(v.x));
        v.y = __uint_as_float(tf32r(v.y));
        v.z = __uint_as_float(tf32r(v.z));
        v.w = __uint_as_float(tf32r(v.w));
        ((float4*)g_w1r)[i] = v;
    }
}

// ---------------- CSR build ----------------
__global__ void k_zero_deg() {
    int i = blockIdx.x * blockDim.x + threadIdx.x;
    if (i < NN) g_deg[i] = 0;
}

__global__ void k_count(const int* __restrict__ ei) {
    int i = blockIdx.x * blockDim.x + threadIdx.x;
    if (i < EE / 4) {
        int4 d = ((const int4*)(ei + EE))[i];
        atomicAdd(&g_deg[d.x], 1);
        atomicAdd(&g_deg[d.y], 1);
        atomicAdd(&g_deg[d.z], 1);
        atomicAdd(&g_deg[d.w], 1);
    }
}

__global__ void k_scan() {
    __shared__ int part[256];
    __shared__ int excl[257];
    int t = threadIdx.x;
    const int CH = (NN + 255) / 256;
    int base = t * CH;
    int s = 0;
    for (int i = 0; i < CH; i++) {
        int idx = base + i;
        if (idx < NN) s += g_deg[idx];
    }
    part[t] = s;
    __syncthreads();
    if (t == 0) {
        int run = 0;
        for (int i = 0; i < 256; i++) { excl[i] = run; run += part[i]; }
        excl[256] = run;
    }
    __syncthreads();
    int off = excl[t];
    for (int i = 0; i < CH; i++) {
        int idx = base + i;
        if (idx < NN) {
            g_off[idx] = off;
            g_cur[idx] = off;
            int d = g_deg[idx];
            off += d;
            g_dinv[idx] = rsqrtf((float)(d + 1));
        }
    }
    if (t == 255) g_off[NN] = excl[256];
}

__global__ void k_scatter(const int* __restrict__ ei) {
    int i = blockIdx.x * blockDim.x + threadIdx.x;
    if (i < EE / 4) {
        int4 sv = ((const int4*)ei)[i];
        int4 dv = ((const int4*)(ei + EE))[i];
        g_srcv[atomicAdd(&g_cur[dv.x], 1)] = sv.x;
        g_srcv[atomicAdd(&g_cur[dv.y], 1)] = sv.y;
        g_srcv[atomicAdd(&g_cur[dv.z], 1)] = sv.z;
        g_srcv[atomicAdd(&g_cur[dv.w], 1)] = sv.w;
    }
}

// ---------------- GEMM1 via mma.sync tf32: features[10000,1000] @ W1r[1000,256] ----------------
// CTA tile M=64, N=128, K=16/stage; 3-stage cp.async; 256 thr, warps 2M x 4N (warp 32x32).
// All loop-carried address math hoisted: loads advance pointers by fixed strides,
// fragment LDS use base+immediate offsets.
#define A_STRIDE 20
#define B_STRIDE 136
#define A_FLOATS (64 * A_STRIDE)              // 1280
#define STAGE_F  (A_FLOATS + 16 * B_STRIDE)   // 3456 floats
#define STAGE_B  (STAGE_F * 4)                // bytes
#define NCH      63

__global__ __launch_bounds__(256) void k_gemm_mma(const float* __restrict__ A) {
    __shared__ __align__(16) float sm[3 * STAGE_F];  // 41472 B
    int tid = threadIdx.x;
    int warp = tid >> 5, lane = tid & 31;
    int g = lane >> 2, tig = lane & 3;
    int wm = (warp >> 2) * 32;       // 0 or 32
    int wn = (warp & 3) * 32;        // 0..96
    int ctaRow0 = blockIdx.y * 64;
    int n0 = blockIdx.x * 128;

    // ---- per-thread load state (chunk-invariant) ----
    int arow = tid >> 2, aseg = tid & 3;
    int agr = ctaRow0 + arow;
    const float* aSrc = A + (size_t)agr * INDIM + aseg * 4;
    uint32_t aDst = smem_u32(sm + arow * A_STRIDE) + aseg * 16;
    int szA_full = (agr < NN) ? 16 : 0;
    int szA_tail = (agr < NN && aseg < 2) ? 16 : 0;   // chunk 62: k = 992,996 valid

    int brow0 = tid >> 5, bseg0 = tid & 31;           // rows 0..7
    int brow1 = (tid + 256) >> 5, bseg1 = bseg0;      // rows 8..15
    const float* bSrc0 = g_w1r + (size_t)brow0 * HID + n0 + bseg0 * 4;
    const float* bSrc1 = g_w1r + (size_t)brow1 * HID + n0 + bseg1 * 4;
    uint32_t bDst0 = smem_u32(sm + A_FLOATS + brow0 * B_STRIDE) + bseg0 * 16;
    uint32_t bDst1 = smem_u32(sm + A_FLOATS + brow1 * B_STRIDE) + bseg1 * 16;
    int szB1_tail = (brow1 < 8) ? 16 : 0;             // chunk 62: rows 8..15 invalid
    // (brow0 < 8 always true -> tail size 16 for j=0)

    uint32_t ldOff = 0;   // rotating stage byte-offset for loads

    // ---- per-thread fragment bases (stage 0) ----
    const float* aFrag0 = sm + (wm + g) * A_STRIDE + tig;
    const float* bFrag0 = sm + A_FLOATS + tig * B_STRIDE + wn + g;

    float d[2][4][4];
#pragma unroll
    for (int mt = 0; mt < 2; mt++)
#pragma unroll
        for (int nt = 0; nt < 4; nt++)
#pragma unroll
            for (int r = 0; r < 4; r++) d[mt][nt][r] = 0.0f;

    // ---- prologue: load chunks 0,1 ----
#pragma unroll
    for (int pc = 0; pc < 2; pc++) {
        cp16(aDst + ldOff, aSrc, szA_full);
        cp16(bDst0 + ldOff, bSrc0, 16);
        cp16(bDst1 + ldOff, bSrc1, 16);
        asm volatile("cp.async.commit_group;" ::: "memory");
        aSrc += 16; bSrc0 += 16 * HID; bSrc1 += 16 * HID;
        ldOff += STAGE_B;
    }

    int csOff = 0;   // rotating stage float-offset for compute
    for (int c = 0; c < NCH; c++) {
        asm volatile("cp.async.wait_group 1;" ::: "memory");
        __syncthreads();
        // issue load for chunk c+2
        if (c + 2 < NCH) {
            int tail = (c + 2 == 62);
            cp16(aDst + ldOff, aSrc, tail ? szA_tail : szA_full);
            cp16(bDst0 + ldOff, bSrc0, 16);
            cp16(bDst1 + ldOff, bSrc1, tail ? szB1_tail : 16);
            aSrc += 16; bSrc0 += 16 * HID; bSrc1 += 16 * HID;
            ldOff += STAGE_B;
            if (ldOff == 3 * STAGE_B) ldOff = 0;
        }
        asm volatile("cp.async.commit_group;" ::: "memory");

        const float* aF = aFrag0 + csOff;
        const float* bF = bFrag0 + csOff;
        csOff += STAGE_F;
        if (csOff == 3 * STAGE_F) csOff = 0;

        // whole-chunk fragment prefetch (32 LDS, base+immediate), then 16 MMAs
        uint32_t af[2][2][4], bf[2][4][2];
#pragma unroll
        for (int ks = 0; ks < 2; ks++) {
            int kb = ks * 8;
#pragma unroll
            for (int mt = 0; mt < 2; mt++) {
                af[ks][mt][0] = tf32r(aF[mt * 16 * A_STRIDE + kb]);
                af[ks][mt][1] = tf32r(aF[(mt * 16 + 8) * A_STRIDE + kb]);
                af[ks][mt][2] = tf32r(aF[mt * 16 * A_STRIDE + kb + 4]);
                af[ks][mt][3] = tf32r(aF[(mt * 16 + 8) * A_STRIDE + kb + 4]);
            }
#pragma unroll
            for (int nt = 0; nt < 4; nt++) {
                bf[ks][nt][0] = __float_as_uint(bF[kb * B_STRIDE + nt * 8]);
                bf[ks][nt][1] = __float_as_uint(bF[(kb + 4) * B_STRIDE + nt * 8]);
            }
        }
#pragma unroll
        for (int ks = 0; ks < 2; ks++)
#pragma unroll
            for (int mt = 0; mt < 2; mt++)
#pragma unroll
                for (int nt = 0; nt < 4; nt++)
                    mma_tf32(d[mt][nt], af[ks][mt], bf[ks][nt]);
    }

#pragma unroll
    for (int mt = 0; mt < 2; mt++) {
        int row0 = ctaRow0 + wm + mt * 16 + g;
#pragma unroll
        for (int nt = 0; nt < 4; nt++) {
            int col = n0 + wn + nt * 8 + 2 * tig;
            if (row0 < NN)
                *(float2*)&g_xw1[(size_t)row0 * HID + col] =
                    make_float2(d[mt][nt][0], d[mt][nt][1]);
            if (row0 + 8 < NN)
                *(float2*)&g_xw1[(size_t)(row0 + 8) * HID + col] =
                    make_float2(d[mt][nt][2], d[mt][nt][3]);
        }
    }
}

// ---------------- fused agg1 + bias + relu + W2 projection -> g_hw2 ----------------
__global__ void k_agg1(const float* __restrict__ b1, const float* __restrict__ W2) {
    int w = (blockIdx.x * blockDim.x + threadIdx.x) >> 5;
    int lane = threadIdx.x & 31;
    if (w >= NN) return;
    float di = g_dinv[w];
    float acc[8];
    const float* xi = g_xw1 + (size_t)w * HID;
#pragma unroll
    for (int u = 0; u < 8; u++) acc[u] = di * xi[u * 32 + lane];
    int p0 = g_off[w], p1 = g_off[w + 1];
    for (int p = p0; p < p1; p++) {
        int s = g_srcv[p];
        float ds = g_dinv[s];
        const float* xs = g_xw1 + (size_t)s * HID;
#pragma unroll
        for (int u = 0; u < 8; u++) acc[u] = fmaf(ds, xs[u * 32 + lane], acc[u]);
    }
    float a0 = 0.f, a1 = 0.f;
#pragma unroll
    for (int u = 0; u < 8; u++) {
        int f = u * 32 + lane;
        float h = fmaxf(fmaf(di, acc[u], b1[f]), 0.0f);
        a0 = fmaf(h, W2[f * 2 + 0], a0);
        a1 = fmaf(h, W2[f * 2 + 1], a1);
    }
#pragma unroll
    for (int o = 16; o > 0; o >>= 1) {
        a0 += __shfl_down_sync(0xffffffffu, a0, o);
        a1 += __shfl_down_sync(0xffffffffu, a1, o);
    }
    if (lane == 0) {
        g_hw2[w * 2 + 0] = a0;
        g_hw2[w * 2 + 1] = a1;
    }
}

// ---------------- agg2 + bias -> emb (d_out) and sq ----------------
__global__ void k_agg2(const float* __restrict__ b2, float* __restrict__ emb) {
    int i = blockIdx.x * blockDim.x + threadIdx.x;
    if (i >= NN) return;
    float di = g_dinv[i];
    float a0 = di * g_hw2[i * 2 + 0];
    float a1 = di * g_hw2[i * 2 + 1];
    int p0 = g_off[i], p1 = g_off[i + 1];
    for (int p = p0; p < p1; p++) {
        int s = g_srcv[p];
        float ds = g_dinv[s];
        a0 = fmaf(ds, g_hw2[s * 2 + 0], a0);
        a1 = fmaf(ds, g_hw2[s * 2 + 1], a1);
    }
    float e0 = fmaf(di, a0, b2[0]);
    float e1 = fmaf(di, a1, b2[1]);
    emb[i * 2 + 0] = e0;
    emb[i * 2 + 1] = e1;
    g_sq[i] = e0 * e0 + e1 * e1;
}

// ---------------- q matrix: q = 1/(1 + 0.5*dist), streaming float4 stores ----------------
#define TJ 1024
#define TI 16

__device__ __forceinline__ float qval(float d2) {
    float d2c = fmaxf(d2, 1e-30f);
    float dist = d2c * rsqrtf(d2c);
    return __fdividef(1.0f, fmaf(0.5f, dist, 1.0f));
}

__global__ __launch_bounds__(256) void k_q(const float* __restrict__ emb,
                                           float* __restrict__ q) {
    __shared__ float sx[TJ], sy[TJ], ss[TJ];
    int j0 = blockIdx.x * TJ;
    int i0 = blockIdx.y * TI;
    int t = threadIdx.x;
#pragma unroll
    for (int v = 0; v < 4; v++) {
        int jl = t + v * 256;
        int jj = j0 + jl;
        if (jj < NN) {
            sx[jl] = emb[jj * 2 + 0];
            sy[jl] = emb[jj * 2 + 1];
            ss[jl] = g_sq[jj];
        }
    }
    __syncthreads();
    int jl = t * 4;
    int j = j0 + jl;
    if (j >= NN) return;
    float x0 = sx[jl], x1 = sx[jl + 1], x2 = sx[jl + 2], x3 = sx[jl + 3];
    float y0 = sy[jl], y1 = sy[jl + 1], y2 = sy[jl + 2], y3 = sy[jl + 3];
    float s0 = ss[jl], s1 = ss[jl + 1], s2 = ss[jl + 2], s3 = ss[jl + 3];
#pragma unroll
    for (int r = 0; r < TI; r++) {
        int i = i0 + r;
        float ex = emb[i * 2 + 0];
        float ey = emb[i * 2 + 1];
        float si = g_sq[i];
        float4 o;
        o.x = qval(si + s0 - 2.0f * fmaf(ex, x0, ey * y0));
        o.y = qval(si + s1 - 2.0f * fmaf(ex, x1, ey * y1));
        o.z = qval(si + s2 - 2.0f * fmaf(ex, x2, ey * y2));
        o.w = qval(si + s3 - 2.0f * fmaf(ex, x3, ey * y3));
        __stcs((float4*)(q + (size_t)i * NN + j), o);
    }
}

// ---------------- launch ----------------
extern "C" void kernel_launch(void* const* d_in, const int* in_sizes, int n_in,
                              void* d_out, int out_size) {
    const float* features = (const float*)d_in[0];
    const int*   ei       = (const int*)d_in[1];
    const float* W1       = (const float*)d_in[2];
    const float* b1       = (const float*)d_in[3];
    const float* W2       = (const float*)d_in[4];
    const float* b2       = (const float*)d_in[5];
    float* out = (float*)d_out;
    float* emb = out;                 // [NN, 2]
    float* q   = out + NN * OUTD;     // [NN, NN]

    k_roundW<<<(INDIM * HID / 4 + 255) / 256, 256>>>(W1);    // 0
    k_zero_deg<<<(NN + 255) / 256, 256>>>();                 // 1
    k_count<<<(EE / 4 + 255) / 256, 256>>>(ei);              // 2

    dim3 gg(HID / 128, (NN + 63) / 64);  // (2, 157) = 314 CTAs
    k_gemm_mma<<<gg, 256>>>(features);                       // 3 (profiled slot)

    k_scan<<<1, 256>>>();                                    // 4
    k_scatter<<<(EE / 4 + 255) / 256, 256>>>(ei);            // 5
    k_agg1<<<(NN * 32 + 255) / 256, 256>>>(b1, W2);          // 6
    k_agg2<<<(NN + 255) / 256, 256>>>(b2, emb);              // 7

    dim3 gq((NN + TJ - 1) / TJ, NN / TI);
    k_q<<<gq, 256>>>(emb, q);                                // 8
}